// round 1
// baseline (speedup 1.0000x reference)
#include <cuda_runtime.h>
#include <cstdint>
#include <cstddef>

// ---------------------------------------------------------------------------
// Problem constants (fixed shapes for this problem)
//   B=256, S=128 -> BS=32768 tokens, H=768, A=512, N=10, C=3, K=3, NUM_ITER=3
// ---------------------------------------------------------------------------
#define BSTOK 32768
#define HDIM  768
#define ADIM  512
#define NTASK 10
#define CCAP  3
#define KCAP  3

// ---------------------------------------------------------------------------
// Scratch (device globals; allocation APIs are forbidden)
// ---------------------------------------------------------------------------
__device__ float g_sem_raw[(size_t)BSTOK * 30];          // pre-squash sem logits (+bias)
__device__ float g_vote[(size_t)BSTOK * 9];              // (K, BS, C) flat
__device__ float g_h2[(size_t)BSTOK * HDIM];             // x + gated capsule output
__device__ float g_a1[(size_t)BSTOK * ADIM];             // after fc1+gelu+gate
__device__ float g_w30[HDIM * 32];                       // sem_w reordered to (H, 32) K-major
__device__ float g_semb[32];                             // sem bias per col

// ---------------------------------------------------------------------------
// Helpers
// ---------------------------------------------------------------------------
__device__ __forceinline__ uint32_t f2tf32(float x) {
    uint32_t u;
    asm("cvt.rna.tf32.f32 %0, %1;" : "=r"(u) : "f"(x));
    return u;
}

__device__ __forceinline__ void mma_tf32(float* c, const uint32_t* a, const uint32_t* b) {
    asm volatile(
        "mma.sync.aligned.m16n8k8.row.col.f32.tf32.tf32.f32 "
        "{%0,%1,%2,%3}, {%4,%5,%6,%7}, {%8,%9}, {%0,%1,%2,%3};"
        : "+f"(c[0]), "+f"(c[1]), "+f"(c[2]), "+f"(c[3])
        : "r"(a[0]), "r"(a[1]), "r"(a[2]), "r"(a[3]), "r"(b[0]), "r"(b[1]));
}

__device__ __forceinline__ float gelu_exact(float v) {
    return 0.5f * v * (1.0f + erff(v * 0.70710678118654752f));
}

__device__ __forceinline__ float sigmoidf_(float z) {
    return 1.0f / (1.0f + expf(-z));
}

// t/s arrive as 1-element tensors; read robustly whether int32 or float32 bits.
__device__ __forceinline__ int read_t(const int* p) {
    int v = *p;
    if (v < 0 || v >= NTASK) v = (int)__int_as_float(v);
    return v;
}
__device__ __forceinline__ float read_s(const int* p) {
    int v = *p;
    if (v >= 0 && v <= 1000000) return (float)v;
    return __int_as_float(v);
}

// ---------------------------------------------------------------------------
// Prep: reorder sem_w (N,H,C) -> W30[h][j], j = c*10+n (cols 30,31 zero-pad),
// and sem bias per column j: sem_b[n, c].
// ---------------------------------------------------------------------------
__global__ void prep_kernel(const float* __restrict__ sem_w, const float* __restrict__ sem_b) {
    int idx = blockIdx.x * blockDim.x + threadIdx.x;
    if (idx < HDIM * 32) {
        int h = idx / 32, j = idx % 32;
        float v = 0.0f;
        if (j < 30) {
            int n = j % NTASK, c = j / NTASK;
            v = sem_w[(size_t)n * HDIM * CCAP + (size_t)h * CCAP + c];
        }
        g_w30[idx] = v;
    } else if (idx < HDIM * 32 + 32) {
        int j = idx - HDIM * 32;
        float v = 0.0f;
        if (j < 30) {
            int n = j % NTASK, c = j / NTASK;
            v = sem_b[n * CCAP + c];
        }
        g_semb[j] = v;
    }
}

// ---------------------------------------------------------------------------
// Generic TF32 tensor-core GEMM with fused epilogues.
//   C[M,N] = epilogue(A[M,K] @ B[K,N])
// EPI 0: sem    -> store cols<30 at ldc=30 with +bias
// EPI 1: fc1    -> gelu(acc+bias) * sigmoid(sf * efull[t*N + c])
// EPI 2: fc2    -> xadd + gelu(acc+bias) * sigmoid(sf * efull[t*N + c])
// ---------------------------------------------------------------------------
template <int BM, int BN, int BK, int WM, int WN, int EPI>
__global__ __launch_bounds__((BM / WM) * (BN / WN) * 32)
void gemm_tf32_kernel(const float* __restrict__ A, const float* __restrict__ Bm,
                      float* __restrict__ C, int M, int N, int K, int ldc,
                      const float* __restrict__ bias, const float* __restrict__ efull,
                      const int* __restrict__ tp, const int* __restrict__ sp,
                      const float* __restrict__ xadd) {
    constexpr int WARPS_M = BM / WM;
    constexpr int WARPS_N = BN / WN;
    constexpr int NTHREADS = WARPS_M * WARPS_N * 32;
    constexpr int MT = WM / 16;
    constexpr int NT = WN / 8;

    __shared__ uint32_t As[BM][BK + 4];
    __shared__ uint32_t Bs[BK][BN + 4];

    const int tid = threadIdx.x;
    const int wid = tid >> 5;
    const int lane = tid & 31;
    const int gr = lane >> 2;   // 0..7
    const int gc = lane & 3;    // 0..3

    const int wm = (wid / WARPS_N) * WM;
    const int wn = (wid % WARPS_N) * WN;
    const int m0 = blockIdx.y * BM;
    const int n0 = blockIdx.x * BN;

    float acc[MT][NT][4];
#pragma unroll
    for (int i = 0; i < MT; i++)
#pragma unroll
        for (int j = 0; j < NT; j++)
#pragma unroll
            for (int q = 0; q < 4; q++) acc[i][j][q] = 0.0f;

    for (int k0 = 0; k0 < K; k0 += BK) {
        // Load A tile (BM x BK), row-major, converted to tf32
#pragma unroll
        for (int e = tid; e < BM * (BK / 4); e += NTHREADS) {
            int r = e / (BK / 4);
            int c4 = (e % (BK / 4)) * 4;
            float4 v = *reinterpret_cast<const float4*>(A + (size_t)(m0 + r) * K + k0 + c4);
            As[r][c4 + 0] = f2tf32(v.x);
            As[r][c4 + 1] = f2tf32(v.y);
            As[r][c4 + 2] = f2tf32(v.z);
            As[r][c4 + 3] = f2tf32(v.w);
        }
        // Load B tile (BK x BN)
#pragma unroll
        for (int e = tid; e < BK * (BN / 4); e += NTHREADS) {
            int r = e / (BN / 4);
            int c4 = (e % (BN / 4)) * 4;
            float4 v = *reinterpret_cast<const float4*>(Bm + (size_t)(k0 + r) * N + n0 + c4);
            Bs[r][c4 + 0] = f2tf32(v.x);
            Bs[r][c4 + 1] = f2tf32(v.y);
            Bs[r][c4 + 2] = f2tf32(v.z);
            Bs[r][c4 + 3] = f2tf32(v.w);
        }
        __syncthreads();

#pragma unroll
        for (int kk = 0; kk < BK; kk += 8) {
            uint32_t af[MT][4];
            uint32_t bf[NT][2];
#pragma unroll
            for (int i = 0; i < MT; i++) {
                int row = wm + i * 16 + gr;
                af[i][0] = As[row][kk + gc];
                af[i][1] = As[row + 8][kk + gc];
                af[i][2] = As[row][kk + gc + 4];
                af[i][3] = As[row + 8][kk + gc + 4];
            }
#pragma unroll
            for (int j = 0; j < NT; j++) {
                int col = wn + j * 8 + gr;
                bf[j][0] = Bs[kk + gc][col];
                bf[j][1] = Bs[kk + gc + 4][col];
            }
#pragma unroll
            for (int i = 0; i < MT; i++)
#pragma unroll
                for (int j = 0; j < NT; j++) mma_tf32(acc[i][j], af[i], bf[j]);
        }
        __syncthreads();
    }

    // ---- epilogue ----
    int tval = 0;
    float sf = 0.0f;
    if (EPI != 0) {
        tval = read_t(tp);
        sf = read_s(sp);
    }

#pragma unroll
    for (int i = 0; i < MT; i++) {
#pragma unroll
        for (int j = 0; j < NT; j++) {
#pragma unroll
            for (int q = 0; q < 4; q++) {
                int r = m0 + wm + i * 16 + gr + ((q >= 2) ? 8 : 0);
                int c = n0 + wn + j * 8 + gc * 2 + (q & 1);
                float v = acc[i][j][q];
                if (EPI == 0) {
                    if (c < 30) C[(size_t)r * ldc + c] = v + bias[c];
                } else {
                    v += bias[c];
                    v = gelu_exact(v);
                    float g = sigmoidf_(sf * efull[(size_t)tval * N + c]);
                    v *= g;
                    if (EPI == 2) v += xadd[(size_t)r * N + c];
                    C[(size_t)r * ldc + c] = v;
                }
            }
        }
    }
}

// ---------------------------------------------------------------------------
// Capsule routing: one thread per token. All tiny math in registers.
// ---------------------------------------------------------------------------
__global__ void routing_kernel(const float* __restrict__ route_w, const int* __restrict__ tp,
                               int M) {
    __shared__ float rw[KCAP * NTASK * CCAP * CCAP];  // 270
    for (int i = threadIdx.x; i < KCAP * NTASK * CCAP * CCAP; i += blockDim.x)
        rw[i] = route_w[i];
    __syncthreads();

    int m = blockIdx.x * blockDim.x + threadIdx.x;
    if (m >= M) return;
    const int tval = read_t(tp);

    // Load sem row and squash per-c over the 10 tasks (flat layout: idx = c*10+n)
    float uf[30];
    const float* sr = g_sem_raw + (size_t)m * 30;
#pragma unroll
    for (int i = 0; i < 30; i++) uf[i] = sr[i];
#pragma unroll
    for (int c = 0; c < CCAP; c++) {
        float sn = 1e-16f;
#pragma unroll
        for (int n = 0; n < NTASK; n++) {
            float v = uf[c * NTASK + n];
            sn += v * v;
        }
        float sc = sqrtf(sn) / (1.0f + sn);
#pragma unroll
        for (int n = 0; n < NTASK; n++) uf[c * NTASK + n] *= sc;
    }
    // u[n][c] = uf[n*3+c]  (pure flat reinterpretation)

    for (int k = 0; k < KCAP; k++) {
        float pr[NTASK][CCAP];
#pragma unroll
        for (int n = 0; n < NTASK; n++) {
#pragma unroll
            for (int d = 0; d < CCAP; d++) {
                float s = 0.0f;
#pragma unroll
                for (int c = 0; c < CCAP; c++)
                    s += uf[n * CCAP + c] * rw[((k * NTASK + n) * CCAP + c) * CCAP + d];
                pr[n][d] = s;
            }
        }

        float lg[NTASK];
#pragma unroll
        for (int n = 0; n < NTASK; n++) lg[n] = 0.0f;
        float vote[CCAP] = {0.0f, 0.0f, 0.0f};

#pragma unroll
        for (int it = 0; it < 3; it++) {
            float ml[NTASK], mx = -1e30f;
#pragma unroll
            for (int n = 0; n < NTASK; n++) {
                ml[n] = (n <= tval) ? lg[n] : -10000.0f;
                mx = fmaxf(mx, ml[n]);
            }
            float p[NTASK], sum = 0.0f;
#pragma unroll
            for (int n = 0; n < NTASK; n++) {
                p[n] = expf(ml[n] - mx);
                sum += p[n];
            }
            float inv = 1.0f / sum;
#pragma unroll
            for (int c = 0; c < CCAP; c++) {
                float s = 0.0f;
#pragma unroll
                for (int n = 0; n < NTASK; n++) s += p[n] * pr[n][c];
                vote[c] = s * inv;
            }
            if (it < 2) {
                float sn = 1e-16f;
#pragma unroll
                for (int c = 0; c < CCAP; c++) sn += vote[c] * vote[c];
                float sc = sqrtf(sn) / (1.0f + sn);
#pragma unroll
                for (int n = 0; n < NTASK; n++) {
                    float s = 0.0f;
#pragma unroll
                    for (int c = 0; c < CCAP; c++) s += pr[n][c] * vote[c];
                    lg[n] += s * sc;
                }
            }
        }
        float* vp = g_vote + ((size_t)k * M + m) * CCAP;
#pragma unroll
        for (int c = 0; c < CCAP; c++) vp[c] = vote[c];
    }
}

// ---------------------------------------------------------------------------
// h2 = x + sigmoid(sf*elarger[t]) * (h9 @ larger_w + larger_b)
// h9[token] = 9 consecutive floats of the flat (K,BS,C) vote buffer.
// One thread per float4 of H.
// ---------------------------------------------------------------------------
__global__ void h2_kernel(const float* __restrict__ x, const float* __restrict__ larger_w,
                          const float* __restrict__ larger_b, const float* __restrict__ elarger,
                          const int* __restrict__ tp, const int* __restrict__ sp, int M) {
    int idx = blockIdx.x * blockDim.x + threadIdx.x;
    const int per_row = HDIM / 4;  // 192
    if (idx >= M * per_row) return;
    int m = idx / per_row;
    int c = (idx % per_row) * 4;

    const int tval = read_t(tp);
    const float sf = read_s(sp);

    float h9[9];
    const float* vp = g_vote + (size_t)m * 9;
#pragma unroll
    for (int j = 0; j < 9; j++) h9[j] = vp[j];

    float4 a = *reinterpret_cast<const float4*>(larger_b + c);
#pragma unroll
    for (int j = 0; j < 9; j++) {
        float4 w = *reinterpret_cast<const float4*>(larger_w + (size_t)j * HDIM + c);
        a.x += h9[j] * w.x;
        a.y += h9[j] * w.y;
        a.z += h9[j] * w.z;
        a.w += h9[j] * w.w;
    }
    float4 e = *reinterpret_cast<const float4*>(elarger + (size_t)tval * HDIM + c);
    a.x *= sigmoidf_(sf * e.x);
    a.y *= sigmoidf_(sf * e.y);
    a.z *= sigmoidf_(sf * e.z);
    a.w *= sigmoidf_(sf * e.w);

    float4 xv = *reinterpret_cast<const float4*>(x + (size_t)m * HDIM + c);
    a.x += xv.x;
    a.y += xv.y;
    a.z += xv.z;
    a.w += xv.w;
    *reinterpret_cast<float4*>(g_h2 + (size_t)m * HDIM + c) = a;
}

// ---------------------------------------------------------------------------
// Launch
// ---------------------------------------------------------------------------
extern "C" void kernel_launch(void* const* d_in, const int* in_sizes, int n_in,
                              void* d_out, int out_size) {
    const float* x        = (const float*)d_in[0];
    const int*   tp       = (const int*)d_in[1];
    const int*   sp       = (const int*)d_in[2];
    const float* fc1_w    = (const float*)d_in[3];
    const float* fc1_b    = (const float*)d_in[4];
    const float* fc2_w    = (const float*)d_in[5];
    const float* fc2_b    = (const float*)d_in[6];
    const float* efc1     = (const float*)d_in[7];
    const float* efc2     = (const float*)d_in[8];
    const float* sem_w    = (const float*)d_in[9];
    const float* sem_b    = (const float*)d_in[10];
    const float* route_w  = (const float*)d_in[11];
    const float* larger_w = (const float*)d_in[12];
    const float* larger_b = (const float*)d_in[13];
    const float* elarger  = (const float*)d_in[14];
    float* out = (float*)d_out;

    const int M = in_sizes[0] / HDIM;  // 32768 tokens

    float *p_sem_raw, *p_h2, *p_a1, *p_w30, *p_semb;
    cudaGetSymbolAddress((void**)&p_sem_raw, g_sem_raw);
    cudaGetSymbolAddress((void**)&p_h2, g_h2);
    cudaGetSymbolAddress((void**)&p_a1, g_a1);
    cudaGetSymbolAddress((void**)&p_w30, g_w30);
    cudaGetSymbolAddress((void**)&p_semb, g_semb);

    // 1) reorder sem weights/bias
    prep_kernel<<<(HDIM * 32 + 32 + 255) / 256, 256>>>(sem_w, sem_b);

    // 2) sem GEMM: x(M,768) @ W30(768,32) -> sem_raw (cols<30)
    gemm_tf32_kernel<128, 32, 32, 32, 16, 0>
        <<<dim3(1, M / 128), 256>>>(x, p_w30, p_sem_raw, M, 32, HDIM, 30,
                                    p_semb, nullptr, nullptr, nullptr, nullptr);

    // 3) dynamic routing (per token)
    routing_kernel<<<(M + 255) / 256, 256>>>(route_w, tp, M);

    // 4) h2 = x + gated capsule projection
    h2_kernel<<<(M * (HDIM / 4) + 255) / 256, 256>>>(x, larger_w, larger_b, elarger, tp, sp, M);

    // 5) fc1: a1 = gelu(h2 @ fc1_w + b) * gate
    gemm_tf32_kernel<128, 64, 32, 32, 32, 1>
        <<<dim3(ADIM / 64, M / 128), 256>>>(p_h2, fc1_w, p_a1, M, ADIM, HDIM, ADIM,
                                            fc1_b, efc1, tp, sp, nullptr);

    // 6) fc2: out = x + gelu(a1 @ fc2_w + b) * gate
    gemm_tf32_kernel<128, 64, 32, 32, 32, 2>
        <<<dim3(HDIM / 64, M / 128), 256>>>(p_a1, fc2_w, out, M, HDIM, ADIM, HDIM,
                                            fc2_b, efc2, tp, sp, x);
}